// round 2
// baseline (speedup 1.0000x reference)
#include <cuda_runtime.h>
#include <math.h>

// ---------------- problem constants ----------------
#define BB      16
#define HH_RES  64
#define W_RES   64
#define CC      512
#define NHEAD   16
#define WH      8
#define WW      8
#define NWTOK   64          // N = WH*WW tokens per window
#define HD      32          // head dim
#define HID     2048
#define NWIN    1024        // total windows = B * 64
#define MTOT    65536       // total tokens = B * 4096
#define PLANE   33554432ull // MTOT * CC  (size of one of q/k/v planes)

#define PI_F    3.14159265358979323846f

// ---------------- scratch (device globals: allocation-free) ----------------
__device__ float g_xnw[(size_t)MTOT * CC];          // LN1 output, window order
__device__ float g_qkv[3ull * MTOT * CC];           // q/k/v planes [which][w][h][n][d]
__device__ float g_attnout[(size_t)MTOT * CC];      // attention output, window order
__device__ float g_x2[(size_t)MTOT * CC];           // x + proj (natural order)
__device__ float g_xm[(size_t)MTOT * CC];           // LN2 output
__device__ float g_hbuf[(size_t)MTOT * HID];        // fc1+gelu output
__device__ float g_aphi[NHEAD * NWTOK * NWTOK];     // A_phi[h][i][j]

// ---------------- window index mapping ----------------
// windowed token m = w*64 + n  ->  natural token g
__device__ __forceinline__ size_t win_to_nat(int m) {
    int w = m >> 6, n = m & 63;
    int b = w >> 6, wy = (w >> 3) & 7, wx = w & 7;
    int ny = n >> 3, nx = n & 7;
    return (size_t)b * 4096 + (size_t)(wy * 8 + ny) * 64 + (wx * 8 + nx);
}

// ---------------- A_phi precompute: [h][i][j] ----------------
__global__ void aphi_kernel(const float* __restrict__ a_p,
                            const float* __restrict__ b_p,
                            float* __restrict__ aphi) {
    int i = blockIdx.x;      // 0..63
    int j = threadIdx.x;     // 0..63
    int xi = i & 7, xj = j & 7;
    int az = xi - xj;                      // [-7, 7]
    int ip = (az + 15) % 15;               // python modulo
    float azf = (float)az * (2.0f * PI_F / (float)W_RES);
    float c = cosf(azf), s = sinf(azf);
#pragma unroll
    for (int h = 0; h < NHEAD; h++) {
        aphi[((h * 64 + i) << 6) + j] = a_p[ip * NHEAD + h] * c + b_p[ip * NHEAD + h] * s;
    }
}

// ---------------- LayerNorm (optionally with window-partition gather) -------
template <int WINDOWED>
__global__ __launch_bounds__(128) void ln_kernel(const float* __restrict__ x,
                                                 const float* __restrict__ gamma,
                                                 const float* __restrict__ beta,
                                                 float* __restrict__ out) {
    int m = blockIdx.x;
    size_t src = WINDOWED ? win_to_nat(m) : (size_t)m;
    int t = threadIdx.x;

    const float4 v = *(const float4*)(x + src * CC + t * 4);
    float s  = v.x + v.y + v.z + v.w;
    float s2 = v.x * v.x + v.y * v.y + v.z * v.z + v.w * v.w;
#pragma unroll
    for (int o = 16; o > 0; o >>= 1) {
        s  += __shfl_down_sync(0xffffffffu, s,  o);
        s2 += __shfl_down_sync(0xffffffffu, s2, o);
    }
    __shared__ float sh[8];
    int wr = t >> 5, ln = t & 31;
    if (ln == 0) { sh[wr] = s; sh[wr + 4] = s2; }
    __syncthreads();
    float ts  = sh[0] + sh[1] + sh[2] + sh[3];
    float ts2 = sh[4] + sh[5] + sh[6] + sh[7];
    float mean = ts * (1.0f / CC);
    float var  = ts2 * (1.0f / CC) - mean * mean;
    float rstd = rsqrtf(var + 1e-5f);

    const float4 g4 = *(const float4*)(gamma + t * 4);
    const float4 b4 = *(const float4*)(beta  + t * 4);
    float4 o4;
    o4.x = (v.x - mean) * rstd * g4.x + b4.x;
    o4.y = (v.y - mean) * rstd * g4.y + b4.y;
    o4.z = (v.z - mean) * rstd * g4.z + b4.z;
    o4.w = (v.w - mean) * rstd * g4.w + b4.w;
    *(float4*)(out + (size_t)m * CC + t * 4) = o4;
}

// ---------------- SGEMM: C[m][n] = sum_k A[m][k] * B[n][k]  + epilogue ------
// A: (M, K) row-major. B: (N, K) row-major (i.e. x @ W.T). 128x128 tile, 8x8/thread.
// EPI: 0 = QKV scatter+bias, 1 = proj + window-reverse + residual,
//      2 = fc1 bias + exact GELU, 3 = fc2 bias + residual.
template <int EPI>
__global__ __launch_bounds__(256) void sgemm_kernel(const float* __restrict__ A,
                                                    const float* __restrict__ B,
                                                    int K,
                                                    const float* __restrict__ bias,
                                                    const float* __restrict__ add,
                                                    float* __restrict__ out) {
    __shared__ float As[8][128];
    __shared__ float Bs[8][128];
    const int bn = blockIdx.x, bm = blockIdx.y;
    const int t = threadIdx.x;
    const int tr = t >> 4, tc = t & 15;     // 16x16 thread grid
    const int arow = t >> 1;                // 0..127
    const int acol = (t & 1) << 2;          // 0 or 4

    const float* Ab = A + ((size_t)bm * 128 + arow) * K;
    const float* Bb = B + ((size_t)bn * 128 + arow) * K;

    float acc[8][8];
#pragma unroll
    for (int i = 0; i < 8; i++)
#pragma unroll
        for (int j = 0; j < 8; j++) acc[i][j] = 0.0f;

    for (int k0 = 0; k0 < K; k0 += 8) {
        float4 av = *(const float4*)(Ab + k0 + acol);
        float4 bv = *(const float4*)(Bb + k0 + acol);
        As[acol + 0][arow] = av.x; As[acol + 1][arow] = av.y;
        As[acol + 2][arow] = av.z; As[acol + 3][arow] = av.w;
        Bs[acol + 0][arow] = bv.x; Bs[acol + 1][arow] = bv.y;
        Bs[acol + 2][arow] = bv.z; Bs[acol + 3][arow] = bv.w;
        __syncthreads();
#pragma unroll
        for (int k = 0; k < 8; k++) {
            float4 a0 = *(const float4*)&As[k][tr * 8];
            float4 a1 = *(const float4*)&As[k][tr * 8 + 4];
            float4 b0 = *(const float4*)&Bs[k][tc * 8];
            float4 b1 = *(const float4*)&Bs[k][tc * 8 + 4];
            float ra[8] = {a0.x, a0.y, a0.z, a0.w, a1.x, a1.y, a1.z, a1.w};
            float rb[8] = {b0.x, b0.y, b0.z, b0.w, b1.x, b1.y, b1.z, b1.w};
#pragma unroll
            for (int i = 0; i < 8; i++)
#pragma unroll
                for (int j = 0; j < 8; j++) acc[i][j] += ra[i] * rb[j];
        }
        __syncthreads();
    }

#pragma unroll
    for (int i = 0; i < 8; i++) {
        int m = bm * 128 + tr * 8 + i;
#pragma unroll
        for (int j = 0; j < 8; j++) {
            int n = bn * 128 + tc * 8 + j;
            float v = acc[i][j];
            if (EPI == 0) {            // QKV: scatter to [which][w][h][nn][d]
                int w = m >> 6, nn = m & 63;
                int which = n >> 9;
                int r = n & 511;
                int h = r >> 5, d = r & 31;
                size_t idx = (size_t)which * PLANE +
                             ((((size_t)w * NHEAD + h) * NWTOK + nn) << 5) + d;
                out[idx] = v + bias[n];
            } else if (EPI == 1) {     // proj: window-reverse + shortcut
                size_t g = win_to_nat(m);
                out[g * CC + n] = v + bias[n] + add[g * CC + n];
            } else if (EPI == 2) {     // fc1 + exact GELU
                float z = v + bias[n];
                out[(size_t)m * HID + n] =
                    0.5f * z * (1.0f + erff(z * 0.70710678118654752440f));
            } else {                   // fc2 + residual
                out[(size_t)m * CC + n] = v + bias[n] + add[(size_t)m * CC + n];
            }
        }
    }
}

// ---------------- fused windowed attention: one block per (window, head) ----
__global__ __launch_bounds__(64) void attn_kernel(const float* __restrict__ D,
                                                  const float* __restrict__ a_r,
                                                  const float* __restrict__ b_r,
                                                  const float* __restrict__ aphi,
                                                  const float* __restrict__ qkv,
                                                  float* __restrict__ outbuf) {
    const int w = blockIdx.x;
    const int h = blockIdx.y;
    const int i = threadIdx.x;          // query row 0..63

    __shared__ float ks[64][32];
    __shared__ float vs[64][32];
    __shared__ float ct[15][64];        // cos(rad * D_j * 2pi/256), rad index = rad+7
    __shared__ float st[15][64];
    __shared__ float arh[15], brh[15];

    const size_t base = ((size_t)(w * NHEAD + h) * NWTOK) << 5;
    const float* qp = qkv + base;
    const float* kp = qkv + PLANE + base;
    const float* vp = qkv + 2ull * PLANE + base;

    const float scale = 0.1767766952966369f;  // 1/sqrt(32)
    float qreg[32];
#pragma unroll
    for (int d4 = 0; d4 < 8; d4++) {
        float4 qv = *(const float4*)(qp + i * 32 + d4 * 4);
        qreg[d4 * 4 + 0] = qv.x * scale; qreg[d4 * 4 + 1] = qv.y * scale;
        qreg[d4 * 4 + 2] = qv.z * scale; qreg[d4 * 4 + 3] = qv.w * scale;
        *(float4*)&ks[i][d4 * 4] = *(const float4*)(kp + i * 32 + d4 * 4);
        *(float4*)&vs[i][d4 * 4] = *(const float4*)(vp + i * 32 + d4 * 4);
    }

    // depth for key token i of this window, then the per-window sincos table
    {
        int b = w >> 6, wy = (w >> 3) & 7, wx = w & 7, ny = i >> 3, nx = i & 7;
        float dj = D[(size_t)b * 4096 + (size_t)(wy * 8 + ny) * 64 + (wx * 8 + nx)];
        const float KR = 2.0f * PI_F / 256.0f;
#pragma unroll
        for (int r = 0; r < 15; r++) {
            float ss, cc;
            __sincosf((float)(r - 7) * dj * KR, &ss, &cc);
            ct[r][i] = cc;
            st[r][i] = ss;
        }
    }
    if (i < 15) { arh[i] = a_r[i * NHEAD + h]; brh[i] = b_r[i * NHEAD + h]; }
    __syncthreads();

    const int yi = i >> 3;
    const float* ap = aphi + ((h * 64 + i) << 6);

    float sreg[64];
    float mx = -1e30f;
#pragma unroll
    for (int j = 0; j < 64; j++) {
        float dot = 0.0f;
#pragma unroll
        for (int d = 0; d < 32; d++) dot += qreg[d] * ks[j][d];
        int yj = j >> 3;
        int rad = yi - yj;                    // [-7,7]
        int ridx = rad + 7;                   // table index
        int ir = rad < 0 ? rad + 15 : rad;    // python modulo for a_r gather
        float s = dot + ap[j] + arh[ir] * ct[ridx][j] + brh[ir] * st[ridx][j];
        sreg[j] = s;
        mx = fmaxf(mx, s);
    }
    float sum = 0.0f;
#pragma unroll
    for (int j = 0; j < 64; j++) {
        float e = expf(sreg[j] - mx);
        sreg[j] = e;
        sum += e;
    }
    float inv = 1.0f / sum;

    float acc[32];
#pragma unroll
    for (int d = 0; d < 32; d++) acc[d] = 0.0f;
#pragma unroll
    for (int j = 0; j < 64; j++) {
        float p = sreg[j];
#pragma unroll
        for (int d4 = 0; d4 < 8; d4++) {
            float4 vv = *(const float4*)&vs[j][d4 * 4];
            acc[d4 * 4 + 0] += p * vv.x; acc[d4 * 4 + 1] += p * vv.y;
            acc[d4 * 4 + 2] += p * vv.z; acc[d4 * 4 + 3] += p * vv.w;
        }
    }
    float* op = outbuf + ((size_t)(w * 64 + i)) * CC + h * 32;
#pragma unroll
    for (int d = 0; d < 32; d++) op[d] = acc[d] * inv;
}

// ---------------- launcher ----------------
extern "C" void kernel_launch(void* const* d_in, const int* in_sizes, int n_in,
                              void* d_out, int out_size) {
    const float* x       = (const float*)d_in[0];
    const float* D       = (const float*)d_in[1];
    const float* norm1_g = (const float*)d_in[2];
    const float* norm1_b = (const float*)d_in[3];
    const float* qkv_w   = (const float*)d_in[4];
    const float* qkv_b   = (const float*)d_in[5];
    const float* proj_w  = (const float*)d_in[6];
    const float* proj_b  = (const float*)d_in[7];
    const float* a_p     = (const float*)d_in[8];
    const float* b_p     = (const float*)d_in[9];
    const float* a_r     = (const float*)d_in[10];
    const float* b_r     = (const float*)d_in[11];
    const float* norm2_g = (const float*)d_in[12];
    const float* norm2_b = (const float*)d_in[13];
    const float* fc1_w   = (const float*)d_in[14];
    const float* fc1_b   = (const float*)d_in[15];
    const float* fc2_w   = (const float*)d_in[16];
    const float* fc2_b   = (const float*)d_in[17];
    float* out = (float*)d_out;

    float *xnw, *qkv, *attno, *x2, *xm, *hbuf, *aphi;
    cudaGetSymbolAddress((void**)&xnw,   g_xnw);
    cudaGetSymbolAddress((void**)&qkv,   g_qkv);
    cudaGetSymbolAddress((void**)&attno, g_attnout);
    cudaGetSymbolAddress((void**)&x2,    g_x2);
    cudaGetSymbolAddress((void**)&xm,    g_xm);
    cudaGetSymbolAddress((void**)&hbuf,  g_hbuf);
    cudaGetSymbolAddress((void**)&aphi,  g_aphi);

    // 1. A_phi tables
    aphi_kernel<<<64, 64>>>(a_p, b_p, aphi);
    // 2. LN1 + window partition
    ln_kernel<1><<<MTOT, 128>>>(x, norm1_g, norm1_b, xnw);
    // 3. QKV GEMM (65536 x 1536 x 512) -> q/k/v planes
    sgemm_kernel<0><<<dim3(12, 512), 256>>>(xnw, qkv_w, 512, qkv_b, nullptr, qkv);
    // 4. windowed attention (1024 windows x 16 heads)
    attn_kernel<<<dim3(NWIN, NHEAD), 64>>>(D, a_r, b_r, aphi, qkv, attno);
    // 5. proj GEMM + window reverse + residual -> x2 (natural order)
    sgemm_kernel<1><<<dim3(4, 512), 256>>>(attno, proj_w, 512, proj_b, x, x2);
    // 6. LN2
    ln_kernel<0><<<MTOT, 128>>>(x2, norm2_g, norm2_b, xm);
    // 7. fc1 GEMM + GELU (65536 x 2048 x 512)
    sgemm_kernel<2><<<dim3(16, 512), 256>>>(xm, fc1_w, 512, fc1_b, nullptr, hbuf);
    // 8. fc2 GEMM + residual -> output (65536 x 512 x 2048)
    sgemm_kernel<3><<<dim3(4, 512), 256>>>(hbuf, fc2_w, 2048, fc2_b, x2, out);
}

// round 5
// speedup vs baseline: 2.1167x; 2.1167x over previous
#include <cuda_runtime.h>
#include <math.h>
#include <stdint.h>

// ---------------- problem constants ----------------
#define BB      16
#define W_RES   64
#define CC      512
#define NHEAD   16
#define NWTOK   64
#define HD      32
#define HID     2048
#define NWIN    1024
#define MTOT    65536
#define PLANE   33554432ull // MTOT * CC

#define PI_F    3.14159265358979323846f

// ---------------- scratch ----------------
__device__ float g_xnw[(size_t)MTOT * CC];
__device__ float g_qkv[3ull * MTOT * CC];
__device__ float g_attnout[(size_t)MTOT * CC];
__device__ float g_x2[(size_t)MTOT * CC];
__device__ float g_xm[(size_t)MTOT * CC];
__device__ float g_hbuf[(size_t)MTOT * HID];
__device__ float g_aphi[NHEAD * NWTOK * NWTOK];

__device__ __forceinline__ size_t win_to_nat(int m) {
    int w = m >> 6, n = m & 63;
    int b = w >> 6, wy = (w >> 3) & 7, wx = w & 7;
    int ny = n >> 3, nx = n & 7;
    return (size_t)b * 4096 + (size_t)(wy * 8 + ny) * 64 + (wx * 8 + nx);
}

// ---------------- A_phi precompute ----------------
__global__ void aphi_kernel(const float* __restrict__ a_p,
                            const float* __restrict__ b_p,
                            float* __restrict__ aphi) {
    int i = blockIdx.x, j = threadIdx.x;
    int az = (i & 7) - (j & 7);
    int ip = (az + 15) % 15;
    float azf = (float)az * (2.0f * PI_F / (float)W_RES);
    float c = cosf(azf), s = sinf(azf);
#pragma unroll
    for (int h = 0; h < NHEAD; h++)
        aphi[((h * 64 + i) << 6) + j] = a_p[ip * NHEAD + h] * c + b_p[ip * NHEAD + h] * s;
}

// ---------------- LayerNorm ----------------
template <int WINDOWED>
__global__ __launch_bounds__(128) void ln_kernel(const float* __restrict__ x,
                                                 const float* __restrict__ gamma,
                                                 const float* __restrict__ beta,
                                                 float* __restrict__ out) {
    int m = blockIdx.x;
    size_t src = WINDOWED ? win_to_nat(m) : (size_t)m;
    int t = threadIdx.x;

    const float4 v = *(const float4*)(x + src * CC + t * 4);
    float s  = v.x + v.y + v.z + v.w;
    float s2 = v.x * v.x + v.y * v.y + v.z * v.z + v.w * v.w;
#pragma unroll
    for (int o = 16; o > 0; o >>= 1) {
        s  += __shfl_down_sync(0xffffffffu, s,  o);
        s2 += __shfl_down_sync(0xffffffffu, s2, o);
    }
    __shared__ float sh[8];
    int wr = t >> 5, ln = t & 31;
    if (ln == 0) { sh[wr] = s; sh[wr + 4] = s2; }
    __syncthreads();
    float ts  = sh[0] + sh[1] + sh[2] + sh[3];
    float ts2 = sh[4] + sh[5] + sh[6] + sh[7];
    float mean = ts * (1.0f / CC);
    float var  = ts2 * (1.0f / CC) - mean * mean;
    float rstd = rsqrtf(var + 1e-5f);

    const float4 g4 = *(const float4*)(gamma + t * 4);
    const float4 b4 = *(const float4*)(beta  + t * 4);
    float4 o4;
    o4.x = (v.x - mean) * rstd * g4.x + b4.x;
    o4.y = (v.y - mean) * rstd * g4.y + b4.y;
    o4.z = (v.z - mean) * rstd * g4.z + b4.z;
    o4.w = (v.w - mean) * rstd * g4.w + b4.w;
    *(float4*)(out + (size_t)m * CC + t * 4) = o4;
}

// ---------------- tf32 tensor-core GEMM ----------------
// C[m][n] = sum_k A[m][k]*B[n][k], 128x128 block tile, 8 warps (2x4),
// warp tile 64x32, mma.m16n8k8.tf32, cp.async double-buffered smem.
// smem layout: As[stage][128][36], Bs[stage][128][36] (row-major, pad 36).

__device__ __forceinline__ void mma_tf32(float* c, const uint32_t* a, const uint32_t* b) {
    asm volatile(
        "mma.sync.aligned.m16n8k8.row.col.f32.tf32.tf32.f32 "
        "{%0,%1,%2,%3}, {%4,%5,%6,%7}, {%8,%9}, {%0,%1,%2,%3};\n"
        : "+f"(c[0]), "+f"(c[1]), "+f"(c[2]), "+f"(c[3])
        : "r"(a[0]), "r"(a[1]), "r"(a[2]), "r"(a[3]), "r"(b[0]), "r"(b[1]));
}
__device__ __forceinline__ void cp16(uint32_t smem, const void* g) {
    asm volatile("cp.async.cg.shared.global [%0], [%1], 16;\n" :: "r"(smem), "l"(g));
}
__device__ __forceinline__ void cp_commit() {
    asm volatile("cp.async.commit_group;\n" ::: "memory");
}
template <int N>
__device__ __forceinline__ void cp_wait() {
    asm volatile("cp.async.wait_group %0;\n" :: "n"(N) : "memory");
}

#define SMSTRIDE 36
#define SM_TILE  (128 * SMSTRIDE)
#define GEMM_SMEM (4 * SM_TILE * 4)   // bytes: 2 stages * (A+B)

template <int EPI>
__global__ __launch_bounds__(256, 2)
void mma_gemm(const float* __restrict__ A, const float* __restrict__ B, int K,
              const float* __restrict__ bias, const float* __restrict__ add,
              float* __restrict__ out) {
    extern __shared__ float smf[];
    float* As = smf;                      // [2][128][36]
    float* Bs = smf + 2 * SM_TILE;

    const int bn = blockIdx.x, bm = blockIdx.y;
    const int t = threadIdx.x;
    const int lane = t & 31, wid = t >> 5;
    const int wm = wid >> 2, wn = wid & 3;
    const int g = lane >> 2, tg = lane & 3;
    const int m_ld = t & 127;
    const int q0 = (t >> 7) << 2;

    const float* Ag = A + (size_t)(bm * 128 + m_ld) * K;
    const float* Bg = B + (size_t)(bn * 128 + m_ld) * K;
    uint32_t sA = (uint32_t)__cvta_generic_to_shared(As);
    uint32_t sB = (uint32_t)__cvta_generic_to_shared(Bs);
    const uint32_t ld_off = (uint32_t)(m_ld * SMSTRIDE) * 4u;

    float c[4][4][4];
#pragma unroll
    for (int a = 0; a < 4; a++)
#pragma unroll
        for (int b = 0; b < 4; b++)
#pragma unroll
            for (int d = 0; d < 4; d++) c[a][b][d] = 0.0f;

    const int nk = K >> 5;

    // prologue: stage 0
    {
        const float* ap = Ag;
        const float* bp = Bg;
#pragma unroll
        for (int r = 0; r < 4; r++) {
            int q = q0 + r;
            cp16(sA + ld_off + q * 16, ap + q * 4);
            cp16(sB + ld_off + q * 16, bp + q * 4);
        }
        cp_commit();
    }

    for (int kc = 0; kc < nk; kc++) {
        if (kc + 1 < nk) {
            int st = (kc + 1) & 1;
            const float* ap = Ag + (kc + 1) * 32;
            const float* bp = Bg + (kc + 1) * 32;
            uint32_t so = (uint32_t)(st * SM_TILE) * 4u + ld_off;
#pragma unroll
            for (int r = 0; r < 4; r++) {
                int q = q0 + r;
                cp16(sA + so + q * 16, ap + q * 4);
                cp16(sB + so + q * 16, bp + q * 4);
            }
            cp_commit();
            cp_wait<1>();
        } else {
            cp_wait<0>();
        }
        __syncthreads();

        const int st = kc & 1;
        const float* Ab = As + st * SM_TILE + (wm * 64) * SMSTRIDE;
        const float* Bb = Bs + st * SM_TILE + (wn * 32) * SMSTRIDE;
#pragma unroll
        for (int ks = 0; ks < 4; ks++) {
            const int kb = ks * 8;
            uint32_t af[4][4], bf[4][2];
#pragma unroll
            for (int mi = 0; mi < 4; mi++) {
                const float* p = Ab + (mi * 16 + g) * SMSTRIDE + kb + tg;
                af[mi][0] = __float_as_uint(p[0]);
                af[mi][1] = __float_as_uint(p[8 * SMSTRIDE]);
                af[mi][2] = __float_as_uint(p[4]);
                af[mi][3] = __float_as_uint(p[8 * SMSTRIDE + 4]);
            }
#pragma unroll
            for (int ni = 0; ni < 4; ni++) {
                const float* p = Bb + (ni * 8 + g) * SMSTRIDE + kb + tg;
                bf[ni][0] = __float_as_uint(p[0]);
                bf[ni][1] = __float_as_uint(p[4]);
            }
#pragma unroll
            for (int mi = 0; mi < 4; mi++)
#pragma unroll
                for (int ni = 0; ni < 4; ni++)
                    mma_tf32(c[mi][ni], af[mi], bf[ni]);
        }
        __syncthreads();
    }

    // ---------------- epilogue ----------------
#pragma unroll
    for (int mi = 0; mi < 4; mi++) {
#pragma unroll
        for (int half = 0; half < 2; half++) {
            const int m = bm * 128 + wm * 64 + mi * 16 + g + half * 8;
#pragma unroll
            for (int ni = 0; ni < 4; ni++) {
                const int n = bn * 128 + wn * 32 + ni * 8 + 2 * tg;
                float v0 = c[mi][ni][half * 2 + 0];
                float v1 = c[mi][ni][half * 2 + 1];
                if (EPI == 0) {            // QKV: bias + scatter to planes
                    float2 o;
                    o.x = v0 + bias[n];
                    o.y = v1 + bias[n + 1];
                    int w = m >> 6, nn = m & 63;
                    int which = n >> 9, r = n & 511;
                    int h = r >> 5, d = r & 31;
                    size_t idx = (size_t)which * PLANE +
                                 ((((size_t)w * NHEAD + h) * NWTOK + nn) << 5) + d;
                    *(float2*)&out[idx] = o;
                } else if (EPI == 1) {     // proj: window-reverse + residual
                    size_t gi = win_to_nat(m);
                    const float2 a2 = *(const float2*)&add[gi * CC + n];
                    float2 o;
                    o.x = v0 + bias[n] + a2.x;
                    o.y = v1 + bias[n + 1] + a2.y;
                    *(float2*)&out[gi * CC + n] = o;
                } else if (EPI == 2) {     // fc1 + exact GELU
                    float z0 = v0 + bias[n];
                    float z1 = v1 + bias[n + 1];
                    float2 o;
                    o.x = 0.5f * z0 * (1.0f + erff(z0 * 0.70710678118654752440f));
                    o.y = 0.5f * z1 * (1.0f + erff(z1 * 0.70710678118654752440f));
                    *(float2*)&out[(size_t)m * HID + n] = o;
                } else {                   // fc2 + residual
                    const float2 a2 = *(const float2*)&add[(size_t)m * CC + n];
                    float2 o;
                    o.x = v0 + bias[n] + a2.x;
                    o.y = v1 + bias[n + 1] + a2.y;
                    *(float2*)&out[(size_t)m * CC + n] = o;
                }
            }
        }
    }
}

// ---------------- fused windowed attention ----------------
__global__ __launch_bounds__(64) void attn_kernel(const float* __restrict__ D,
                                                  const float* __restrict__ a_r,
                                                  const float* __restrict__ b_r,
                                                  const float* __restrict__ aphi,
                                                  const float* __restrict__ qkv,
                                                  float* __restrict__ outbuf) {
    const int w = blockIdx.x;
    const int h = blockIdx.y;
    const int i = threadIdx.x;

    __shared__ float ks[64][32];
    __shared__ float vs[64][32];
    __shared__ float ct[15][64];
    __shared__ float st[15][64];
    __shared__ float arh[15], brh[15];

    const size_t base = ((size_t)(w * NHEAD + h) * NWTOK) << 5;
    const float* qp = qkv + base;
    const float* kp = qkv + PLANE + base;
    const float* vp = qkv + 2ull * PLANE + base;

    const float scale = 0.1767766952966369f;
    float qreg[32];
#pragma unroll
    for (int d4 = 0; d4 < 8; d4++) {
        float4 qv = *(const float4*)(qp + i * 32 + d4 * 4);
        qreg[d4 * 4 + 0] = qv.x * scale; qreg[d4 * 4 + 1] = qv.y * scale;
        qreg[d4 * 4 + 2] = qv.z * scale; qreg[d4 * 4 + 3] = qv.w * scale;
        *(float4*)&ks[i][d4 * 4] = *(const float4*)(kp + i * 32 + d4 * 4);
        *(float4*)&vs[i][d4 * 4] = *(const float4*)(vp + i * 32 + d4 * 4);
    }

    {
        int b = w >> 6, wy = (w >> 3) & 7, wx = w & 7, ny = i >> 3, nx = i & 7;
        float dj = D[(size_t)b * 4096 + (size_t)(wy * 8 + ny) * 64 + (wx * 8 + nx)];
        const float KR = 2.0f * PI_F / 256.0f;
#pragma unroll
        for (int r = 0; r < 15; r++) {
            float ss, cc;
            __sincosf((float)(r - 7) * dj * KR, &ss, &cc);
            ct[r][i] = cc;
            st[r][i] = ss;
        }
    }
    if (i < 15) { arh[i] = a_r[i * NHEAD + h]; brh[i] = b_r[i * NHEAD + h]; }
    __syncthreads();

    const int yi = i >> 3;
    const float* ap = aphi + ((h * 64 + i) << 6);

    float sreg[64];
    float mx = -1e30f;
#pragma unroll
    for (int j = 0; j < 64; j++) {
        float dot = 0.0f;
#pragma unroll
        for (int d = 0; d < 32; d++) dot += qreg[d] * ks[j][d];
        int yj = j >> 3;
        int rad = yi - yj;
        int ridx = rad + 7;
        int ir = rad < 0 ? rad + 15 : rad;
        float s = dot + ap[j] + arh[ir] * ct[ridx][j] + brh[ir] * st[ridx][j];
        sreg[j] = s;
        mx = fmaxf(mx, s);
    }
    float sum = 0.0f;
#pragma unroll
    for (int j = 0; j < 64; j++) {
        float e = expf(sreg[j] - mx);
        sreg[j] = e;
        sum += e;
    }
    float inv = 1.0f / sum;

    float acc[32];
#pragma unroll
    for (int d = 0; d < 32; d++) acc[d] = 0.0f;
#pragma unroll
    for (int j = 0; j < 64; j++) {
        float p = sreg[j];
#pragma unroll
        for (int d4 = 0; d4 < 8; d4++) {
            float4 vv = *(const float4*)&vs[j][d4 * 4];
            acc[d4 * 4 + 0] += p * vv.x; acc[d4 * 4 + 1] += p * vv.y;
            acc[d4 * 4 + 2] += p * vv.z; acc[d4 * 4 + 3] += p * vv.w;
        }
    }
    float* op = outbuf + ((size_t)(w * 64 + i)) * CC + h * 32;
#pragma unroll
    for (int d = 0; d < 32; d++) op[d] = acc[d] * inv;
}

// ---------------- launcher ----------------
extern "C" void kernel_launch(void* const* d_in, const int* in_sizes, int n_in,
                              void* d_out, int out_size) {
    const float* x       = (const float*)d_in[0];
    const float* D       = (const float*)d_in[1];
    const float* norm1_g = (const float*)d_in[2];
    const float* norm1_b = (const float*)d_in[3];
    const float* qkv_w   = (const float*)d_in[4];
    const float* qkv_b   = (const float*)d_in[5];
    const float* proj_w  = (const float*)d_in[6];
    const float* proj_b  = (const float*)d_in[7];
    const float* a_p     = (const float*)d_in[8];
    const float* b_p     = (const float*)d_in[9];
    const float* a_r     = (const float*)d_in[10];
    const float* b_r     = (const float*)d_in[11];
    const float* norm2_g = (const float*)d_in[12];
    const float* norm2_b = (const float*)d_in[13];
    const float* fc1_w   = (const float*)d_in[14];
    const float* fc1_b   = (const float*)d_in[15];
    const float* fc2_w   = (const float*)d_in[16];
    const float* fc2_b   = (const float*)d_in[17];
    float* out = (float*)d_out;

    float *xnw, *qkv, *attno, *x2, *xm, *hbuf, *aphi;
    cudaGetSymbolAddress((void**)&xnw,   g_xnw);
    cudaGetSymbolAddress((void**)&qkv,   g_qkv);
    cudaGetSymbolAddress((void**)&attno, g_attnout);
    cudaGetSymbolAddress((void**)&x2,    g_x2);
    cudaGetSymbolAddress((void**)&xm,    g_xm);
    cudaGetSymbolAddress((void**)&hbuf,  g_hbuf);
    cudaGetSymbolAddress((void**)&aphi,  g_aphi);

    static int smem_set = 0;
    if (!smem_set) {
        cudaFuncSetAttribute(mma_gemm<0>, cudaFuncAttributeMaxDynamicSharedMemorySize, GEMM_SMEM);
        cudaFuncSetAttribute(mma_gemm<1>, cudaFuncAttributeMaxDynamicSharedMemorySize, GEMM_SMEM);
        cudaFuncSetAttribute(mma_gemm<2>, cudaFuncAttributeMaxDynamicSharedMemorySize, GEMM_SMEM);
        cudaFuncSetAttribute(mma_gemm<3>, cudaFuncAttributeMaxDynamicSharedMemorySize, GEMM_SMEM);
        smem_set = 1;
    }

    aphi_kernel<<<64, 64>>>(a_p, b_p, aphi);
    ln_kernel<1><<<MTOT, 128>>>(x, norm1_g, norm1_b, xnw);
    mma_gemm<0><<<dim3(12, 512), 256, GEMM_SMEM>>>(xnw, qkv_w, 512, qkv_b, nullptr, qkv);
    attn_kernel<<<dim3(NWIN, NHEAD), 64>>>(D, a_r, b_r, aphi, qkv, attno);
    mma_gemm<1><<<dim3(4, 512), 256, GEMM_SMEM>>>(attno, proj_w, 512, proj_b, x, x2);
    ln_kernel<0><<<MTOT, 128>>>(x2, norm2_g, norm2_b, xm);
    mma_gemm<2><<<dim3(16, 512), 256, GEMM_SMEM>>>(xm, fc1_w, 512, fc1_b, nullptr, hbuf);
    mma_gemm<3><<<dim3(4, 512), 256, GEMM_SMEM>>>(hbuf, fc2_w, 2048, fc2_b, x2, out);
}

// round 7
// speedup vs baseline: 5.0679x; 2.3943x over previous
#include <cuda_runtime.h>
#include <cuda_fp16.h>
#include <math.h>
#include <stdint.h>

// ---------------- problem constants ----------------
#define BB      16
#define W_RES   64
#define CC      512
#define NHEAD   16
#define NWTOK   64
#define HD      32
#define HID     2048
#define NWIN    1024
#define MTOT    65536
#define PLANE   33554432ull // MTOT * CC

#define PI_F    3.14159265358979323846f

// ---------------- scratch ----------------
__device__ float g_xnw[(size_t)MTOT * CC];      // reused as __half (LN1 out)
__device__ float g_qkv[3ull * MTOT * CC];       // fp32 q/k/v planes
__device__ float g_attnout[(size_t)MTOT * CC];  // reused as __half
__device__ float g_x2[(size_t)MTOT * CC];       // fp32 (residual)
__device__ float g_xm[(size_t)MTOT * CC];       // reused as __half (LN2 out)
__device__ float g_hbuf[(size_t)MTOT * HID];    // reused as __half (gelu out)
__device__ float g_aphi[NHEAD * NWTOK * NWTOK];
__device__ __half g_wh[3145728];                // fp16 weights: qkv|proj|fc1|fc2

#define WH_QKV  0
#define WH_PROJ 786432
#define WH_FC1  1048576
#define WH_FC2  2097152

__device__ __forceinline__ size_t win_to_nat(int m) {
    int w = m >> 6, n = m & 63;
    int b = w >> 6, wy = (w >> 3) & 7, wx = w & 7;
    int ny = n >> 3, nx = n & 7;
    return (size_t)b * 4096 + (size_t)(wy * 8 + ny) * 64 + (wx * 8 + nx);
}

// ---------------- PTX helpers ----------------
__device__ __forceinline__ uint32_t smem_u32(const void* p) {
    uint32_t a;
    asm("{ .reg .u64 tmp; cvta.to.shared.u64 tmp, %1; cvt.u32.u64 %0, tmp; }"
        : "=r"(a) : "l"(p));
    return a;
}
__device__ __forceinline__ void cp16(uint32_t smem, const void* g) {
    asm volatile("cp.async.cg.shared.global [%0], [%1], 16;\n" :: "r"(smem), "l"(g));
}
__device__ __forceinline__ void cp_commit() {
    asm volatile("cp.async.commit_group;\n" ::: "memory");
}
template <int N>
__device__ __forceinline__ void cp_wait() {
    asm volatile("cp.async.wait_group %0;\n" :: "n"(N) : "memory");
}
__device__ __forceinline__ void ldsm_x4(uint32_t* r, uint32_t addr) {
    asm volatile("ldmatrix.sync.aligned.m8n8.x4.shared.b16 {%0,%1,%2,%3}, [%4];"
                 : "=r"(r[0]), "=r"(r[1]), "=r"(r[2]), "=r"(r[3]) : "r"(addr));
}
__device__ __forceinline__ void ldsm_x2(uint32_t* r, uint32_t addr) {
    asm volatile("ldmatrix.sync.aligned.m8n8.x2.shared.b16 {%0,%1}, [%2];"
                 : "=r"(r[0]), "=r"(r[1]) : "r"(addr));
}
__device__ __forceinline__ void mma_f16(float* c, const uint32_t* a, const uint32_t* b) {
    asm volatile(
        "mma.sync.aligned.m16n8k16.row.col.f32.f16.f16.f32 "
        "{%0,%1,%2,%3}, {%4,%5,%6,%7}, {%8,%9}, {%0,%1,%2,%3};\n"
        : "+f"(c[0]), "+f"(c[1]), "+f"(c[2]), "+f"(c[3])
        : "r"(a[0]), "r"(a[1]), "r"(a[2]), "r"(a[3]), "r"(b[0]), "r"(b[1]));
}

// ---------------- weight fp32 -> fp16 ----------------
__global__ void w2h_kernel(const float* __restrict__ w, __half* __restrict__ o, int n) {
    for (int i = blockIdx.x * blockDim.x + threadIdx.x; i < n; i += gridDim.x * blockDim.x)
        o[i] = __float2half_rn(w[i]);
}

// ---------------- A_phi precompute ----------------
__global__ void aphi_kernel(const float* __restrict__ a_p,
                            const float* __restrict__ b_p,
                            float* __restrict__ aphi) {
    int i = blockIdx.x, j = threadIdx.x;
    int az = (i & 7) - (j & 7);
    int ip = (az + 15) % 15;
    float azf = (float)az * (2.0f * PI_F / (float)W_RES);
    float c = cosf(azf), s = sinf(azf);
#pragma unroll
    for (int h = 0; h < NHEAD; h++)
        aphi[((h * 64 + i) << 6) + j] = a_p[ip * NHEAD + h] * c + b_p[ip * NHEAD + h] * s;
}

// ---------------- LayerNorm (fp32 in, fp16 out) ----------------
template <int WINDOWED>
__global__ __launch_bounds__(128) void ln_kernel(const float* __restrict__ x,
                                                 const float* __restrict__ gamma,
                                                 const float* __restrict__ beta,
                                                 __half* __restrict__ out) {
    int m = blockIdx.x;
    size_t src = WINDOWED ? win_to_nat(m) : (size_t)m;
    int t = threadIdx.x;

    const float4 v = *(const float4*)(x + src * CC + t * 4);
    float s  = v.x + v.y + v.z + v.w;
    float s2 = v.x * v.x + v.y * v.y + v.z * v.z + v.w * v.w;
#pragma unroll
    for (int o = 16; o > 0; o >>= 1) {
        s  += __shfl_down_sync(0xffffffffu, s,  o);
        s2 += __shfl_down_sync(0xffffffffu, s2, o);
    }
    __shared__ float sh[8];
    int wr = t >> 5, ln = t & 31;
    if (ln == 0) { sh[wr] = s; sh[wr + 4] = s2; }
    __syncthreads();
    float ts  = sh[0] + sh[1] + sh[2] + sh[3];
    float ts2 = sh[4] + sh[5] + sh[6] + sh[7];
    float mean = ts * (1.0f / CC);
    float var  = ts2 * (1.0f / CC) - mean * mean;
    float rstd = rsqrtf(var + 1e-5f);

    const float4 g4 = *(const float4*)(gamma + t * 4);
    const float4 b4 = *(const float4*)(beta  + t * 4);
    __half2 p0 = __floats2half2_rn((v.x - mean) * rstd * g4.x + b4.x,
                                   (v.y - mean) * rstd * g4.y + b4.y);
    __half2 p1 = __floats2half2_rn((v.z - mean) * rstd * g4.z + b4.z,
                                   (v.w - mean) * rstd * g4.w + b4.w);
    *(__half2*)(out + (size_t)m * CC + t * 4)     = p0;
    *(__half2*)(out + (size_t)m * CC + t * 4 + 2) = p1;
}

// ---------------- fp16 tensor-core GEMM ----------------
// C[m][n] = sum_k A[m][k]*B[n][k]; A(M,K), B(N,K) both fp16 row-major.
// 128x128 CTA tile, 8 warps (2x4), warp tile 64x32, mma.m16n8k16, fp32 acc.
// smem: per stage A 128x72h + B 128x72h (rows padded 64->72 halves, 144B).
// Double-buffered cp.async.

#define STRH      72
#define ROWB      144
#define A_ST_B    (128 * ROWB)          // 18432 bytes
#define STAGE_B   (2 * A_ST_B)          // 36864 bytes (A+B)
#define HGEMM_SMEM (2 * STAGE_B)        // 73728 bytes

template <int EPI>
__global__ __launch_bounds__(256, 2)
void hgemm(const __half* __restrict__ A, const __half* __restrict__ B, int K,
           const float* __restrict__ bias, const float* __restrict__ add,
           float* __restrict__ out) {
    extern __shared__ __half sh[];
    const uint32_t sbase = smem_u32(sh);

    const int bn = blockIdx.x, bm = blockIdx.y;
    const int t = threadIdx.x;
    const int lane = t & 31, wid = t >> 5;
    const int wm = wid >> 2, wn = wid & 3;
    const int g = lane >> 2, tg = lane & 3;

    const __half* Ag = A + (size_t)(bm * 128) * K;
    const __half* Bg = B + (size_t)(bn * 128) * K;

    float c[4][4][4];
#pragma unroll
    for (int a = 0; a < 4; a++)
#pragma unroll
        for (int b = 0; b < 4; b++)
#pragma unroll
            for (int d = 0; d < 4; d++) c[a][b][d] = 0.0f;

    const int nk = K >> 6;               // K-chunk = 64 halves

    auto load_stage = [&](int cidx) {
        const uint32_t sb = sbase + (uint32_t)(cidx & 1) * STAGE_B;
        const __half* Ac = Ag + cidx * 64;
        const __half* Bc = Bg + cidx * 64;
#pragma unroll
        for (int i = 0; i < 4; i++) {
            int gr = i * 256 + t;
            int row = gr >> 3, q = gr & 7;
            cp16(sb + row * ROWB + q * 16, Ac + (size_t)row * K + q * 8);
        }
#pragma unroll
        for (int i = 0; i < 4; i++) {
            int gr = i * 256 + t;
            int row = gr >> 3, q = gr & 7;
            cp16(sb + A_ST_B + row * ROWB + q * 16, Bc + (size_t)row * K + q * 8);
        }
        cp_commit();
    };

    load_stage(0);

    for (int cc = 0; cc < nk; cc++) {
        if (cc + 1 < nk) { load_stage(cc + 1); cp_wait<1>(); }
        else             { cp_wait<0>(); }
        __syncthreads();

        const uint32_t sb = sbase + (uint32_t)(cc & 1) * STAGE_B;
        const uint32_t aoff = sb + (wm * 64 + (lane & 15)) * ROWB + (lane >> 4) * 16;
        const uint32_t boff = sb + A_ST_B + (wn * 32 + (lane & 7)) * ROWB + ((lane >> 3) & 1) * 16;

#pragma unroll
        for (int ks = 0; ks < 4; ks++) {
            const uint32_t kb = ks * 32;   // 16 halves = 32 bytes per k-step
            uint32_t af[4][4], bf[4][2];
#pragma unroll
            for (int mi = 0; mi < 4; mi++) ldsm_x4(af[mi], aoff + mi * (16 * ROWB) + kb);
#pragma unroll
            for (int ni = 0; ni < 4; ni++) ldsm_x2(bf[ni], boff + ni * (8 * ROWB) + kb);
#pragma unroll
            for (int mi = 0; mi < 4; mi++)
#pragma unroll
                for (int ni = 0; ni < 4; ni++)
                    mma_f16(c[mi][ni], af[mi], bf[ni]);
        }
        __syncthreads();
    }

    // ---------------- epilogue ----------------
#pragma unroll
    for (int mi = 0; mi < 4; mi++) {
#pragma unroll
        for (int half = 0; half < 2; half++) {
            const int m = bm * 128 + wm * 64 + mi * 16 + g + half * 8;
#pragma unroll
            for (int ni = 0; ni < 4; ni++) {
                const int n = bn * 128 + wn * 32 + ni * 8 + 2 * tg;
                float v0 = c[mi][ni][half * 2 + 0];
                float v1 = c[mi][ni][half * 2 + 1];
                if (EPI == 0) {            // QKV: bias + scatter to fp32 planes
                    float2 o;
                    o.x = v0 + bias[n];
                    o.y = v1 + bias[n + 1];
                    int w = m >> 6, nn = m & 63;
                    int which = n >> 9, r = n & 511;
                    int h = r >> 5, d = r & 31;
                    size_t idx = (size_t)which * PLANE +
                                 ((((size_t)w * NHEAD + h) * NWTOK + nn) << 5) + d;
                    *(float2*)&out[idx] = o;
                } else if (EPI == 1) {     // proj: window-reverse + residual (fp32)
                    size_t gi = win_to_nat(m);
                    const float2 a2 = *(const float2*)&add[gi * CC + n];
                    float2 o;
                    o.x = v0 + bias[n] + a2.x;
                    o.y = v1 + bias[n + 1] + a2.y;
                    *(float2*)&out[gi * CC + n] = o;
                } else if (EPI == 2) {     // fc1 + exact GELU -> fp16
                    float z0 = v0 + bias[n];
                    float z1 = v1 + bias[n + 1];
                    float g0 = 0.5f * z0 * (1.0f + erff(z0 * 0.70710678118654752440f));
                    float g1 = 0.5f * z1 * (1.0f + erff(z1 * 0.70710678118654752440f));
                    __half* oh = (__half*)out;
                    *(__half2*)&oh[(size_t)m * HID + n] = __floats2half2_rn(g0, g1);
                } else {                   // fc2 + residual (fp32 final)
                    const float2 a2 = *(const float2*)&add[(size_t)m * CC + n];
                    float2 o;
                    o.x = v0 + bias[n] + a2.x;
                    o.y = v1 + bias[n + 1] + a2.y;
                    *(float2*)&out[(size_t)m * CC + n] = o;
                }
            }
        }
    }
}

// ---------------- fused windowed attention (fp32 in, fp16 out) ----------------
__global__ __launch_bounds__(64) void attn_kernel(const float* __restrict__ D,
                                                  const float* __restrict__ a_r,
                                                  const float* __restrict__ b_r,
                                                  const float* __restrict__ aphi,
                                                  const float* __restrict__ qkv,
                                                  __half* __restrict__ outbuf) {
    const int w = blockIdx.x;
    const int h = blockIdx.y;
    const int i = threadIdx.x;

    __shared__ float ks[64][32];
    __shared__ float vs[64][32];
    __shared__ float ct[15][64];
    __shared__ float st[15][64];
    __shared__ float arh[15], brh[15];

    const size_t base = ((size_t)(w * NHEAD + h) * NWTOK) << 5;
    const float* qp = qkv + base;
    const float* kp = qkv + PLANE + base;
    const float* vp = qkv + 2ull * PLANE + base;

    const float scale = 0.1767766952966369f;
    float qreg[32];
#pragma unroll
    for (int d4 = 0; d4 < 8; d4++) {
        float4 qv = *(const float4*)(qp + i * 32 + d4 * 4);
        qreg[d4 * 4 + 0] = qv.x * scale; qreg[d4 * 4 + 1] = qv.y * scale;
        qreg[d4 * 4 + 2] = qv.z * scale; qreg[d4 * 4 + 3] = qv.w * scale;
        *(float4*)&ks[i][d4 * 4] = *(const float4*)(kp + i * 32 + d4 * 4);
        *(float4*)&vs[i][d4 * 4] = *(const float4*)(vp + i * 32 + d4 * 4);
    }

    {
        int b = w >> 6, wy = (w >> 3) & 7, wx = w & 7, ny = i >> 3, nx = i & 7;
        float dj = D[(size_t)b * 4096 + (size_t)(wy * 8 + ny) * 64 + (wx * 8 + nx)];
        const float KR = 2.0f * PI_F / 256.0f;
#pragma unroll
        for (int r = 0; r < 15; r++) {
            float ss, cc;
            __sincosf((float)(r - 7) * dj * KR, &ss, &cc);
            ct[r][i] = cc;
            st[r][i] = ss;
        }
    }
    if (i < 15) { arh[i] = a_r[i * NHEAD + h]; brh[i] = b_r[i * NHEAD + h]; }
    __syncthreads();

    const int yi = i >> 3;
    const float* ap = aphi + ((h * 64 + i) << 6);

    float sreg[64];
    float mx = -1e30f;
#pragma unroll
    for (int j = 0; j < 64; j++) {
        const float4* kq = (const float4*)ks[j];
        float dot = 0.0f;
#pragma unroll
        for (int d4 = 0; d4 < 8; d4++) {
            float4 kv = kq[d4];
            dot += qreg[4 * d4 + 0] * kv.x + qreg[4 * d4 + 1] * kv.y +
                   qreg[4 * d4 + 2] * kv.z + qreg[4 * d4 + 3] * kv.w;
        }
        int yj = j >> 3;
        int rad = yi - yj;
        int ridx = rad + 7;
        int ir = rad < 0 ? rad + 15 : rad;
        float s = dot + ap[j] + arh[ir] * ct[ridx][j] + brh[ir] * st[ridx][j];
        sreg[j] = s;
        mx = fmaxf(mx, s);
    }
    float sum = 0.0f;
#pragma unroll
    for (int j = 0; j < 64; j++) {
        float e = expf(sreg[j] - mx);
        sreg[j] = e;
        sum += e;
    }
    float inv = 1.0f / sum;

    float acc[32];
#pragma unroll
    for (int d = 0; d < 32; d++) acc[d] = 0.0f;
#pragma unroll
    for (int j = 0; j < 64; j++) {
        float p = sreg[j];
        const float4* vq = (const float4*)vs[j];
#pragma unroll
        for (int d4 = 0; d4 < 8; d4++) {
            float4 vv = vq[d4];
            acc[d4 * 4 + 0] += p * vv.x; acc[d4 * 4 + 1] += p * vv.y;
            acc[d4 * 4 + 2] += p * vv.z; acc[d4 * 4 + 3] += p * vv.w;
        }
    }
    __half2* op = (__half2*)(outbuf + ((size_t)(w * 64 + i)) * CC + h * 32);
#pragma unroll
    for (int d = 0; d < 16; d++)
        op[d] = __floats2half2_rn(acc[2 * d] * inv, acc[2 * d + 1] * inv);
}

// ---------------- launcher ----------------
extern "C" void kernel_launch(void* const* d_in, const int* in_sizes, int n_in,
                              void* d_out, int out_size) {
    const float* x       = (const float*)d_in[0];
    const float* D       = (const float*)d_in[1];
    const float* norm1_g = (const float*)d_in[2];
    const float* norm1_b = (const float*)d_in[3];
    const float* qkv_w   = (const float*)d_in[4];
    const float* qkv_b   = (const float*)d_in[5];
    const float* proj_w  = (const float*)d_in[6];
    const float* proj_b  = (const float*)d_in[7];
    const float* a_p     = (const float*)d_in[8];
    const float* b_p     = (const float*)d_in[9];
    const float* a_r     = (const float*)d_in[10];
    const float* b_r     = (const float*)d_in[11];
    const float* norm2_g = (const float*)d_in[12];
    const float* norm2_b = (const float*)d_in[13];
    const float* fc1_w   = (const float*)d_in[14];
    const float* fc1_b   = (const float*)d_in[15];
    const float* fc2_w   = (const float*)d_in[16];
    const float* fc2_b   = (const float*)d_in[17];
    float* out = (float*)d_out;

    float *xnw, *qkv, *attno, *x2, *xm, *hbuf, *aphi;
    __half* wh;
    cudaGetSymbolAddress((void**)&xnw,   g_xnw);
    cudaGetSymbolAddress((void**)&qkv,   g_qkv);
    cudaGetSymbolAddress((void**)&attno, g_attnout);
    cudaGetSymbolAddress((void**)&x2,    g_x2);
    cudaGetSymbolAddress((void**)&xm,    g_xm);
    cudaGetSymbolAddress((void**)&hbuf,  g_hbuf);
    cudaGetSymbolAddress((void**)&aphi,  g_aphi);
    cudaGetSymbolAddress((void**)&wh,    g_wh);

    __half* xnw_h   = (__half*)xnw;
    __half* attno_h = (__half*)attno;
    __half* xm_h    = (__half*)xm;
    __half* hbuf_h  = (__half*)hbuf;

    static int smem_set = 0;
    if (!smem_set) {
        cudaFuncSetAttribute(hgemm<0>, cudaFuncAttributeMaxDynamicSharedMemorySize, HGEMM_SMEM);
        cudaFuncSetAttribute(hgemm<1>, cudaFuncAttributeMaxDynamicSharedMemorySize, HGEMM_SMEM);
        cudaFuncSetAttribute(hgemm<2>, cudaFuncAttributeMaxDynamicSharedMemorySize, HGEMM_SMEM);
        cudaFuncSetAttribute(hgemm<3>, cudaFuncAttributeMaxDynamicSharedMemorySize, HGEMM_SMEM);
        smem_set = 1;
    }

    // weight conversions
    w2h_kernel<<<384, 256>>>(qkv_w,  wh + WH_QKV,  786432);
    w2h_kernel<<<128, 256>>>(proj_w, wh + WH_PROJ, 262144);
    w2h_kernel<<<512, 256>>>(fc1_w,  wh + WH_FC1,  1048576);
    w2h_kernel<<<512, 256>>>(fc2_w,  wh + WH_FC2,  1048576);

    aphi_kernel<<<64, 64>>>(a_p, b_p, aphi);
    ln_kernel<1><<<MTOT, 128>>>(x, norm1_g, norm1_b, xnw_h);
    hgemm<0><<<dim3(12, 512), 256, HGEMM_SMEM>>>(xnw_h, wh + WH_QKV, 512, qkv_b, nullptr, qkv);
    attn_kernel<<<dim3(NWIN, NHEAD), 64>>>(D, a_r, b_r, aphi, qkv, attno_h);
    hgemm<1><<<dim3(4, 512), 256, HGEMM_SMEM>>>(attno_h, wh + WH_PROJ, 512, proj_b, x, x2);
    ln_kernel<0><<<MTOT, 128>>>(x2, norm2_g, norm2_b, xm_h);
    hgemm<2><<<dim3(16, 512), 256, HGEMM_SMEM>>>(xm_h, wh + WH_FC1, 512, fc1_b, nullptr, (float*)hbuf_h);
    hgemm<3><<<dim3(4, 512), 256, HGEMM_SMEM>>>(hbuf_h, wh + WH_FC2, 2048, fc2_b, x2, out);
}

// round 11
// speedup vs baseline: 6.8132x; 1.3444x over previous
#include <cuda_runtime.h>
#include <cuda_fp16.h>
#include <math.h>
#include <stdint.h>

// ---------------- problem constants ----------------
#define BB      16
#define W_RES   64
#define CC      512
#define NHEAD   16
#define NWTOK   64
#define HD      32
#define HID     2048
#define NWIN    1024
#define MTOT    65536
#define PLANE   33554432ull // MTOT * CC elements per q/k/v plane

#define PI_F    3.14159265358979323846f

// ---------------- scratch ----------------
__device__ float g_xnw[(size_t)MTOT * CC];      // as __half (LN1 out)
__device__ float g_qkv[3ull * MTOT * CC];       // as __half q/k/v planes
__device__ float g_attnout[(size_t)MTOT * CC];  // as __half
__device__ float g_x2[(size_t)MTOT * CC];       // fp32 (residual)
__device__ float g_xm[(size_t)MTOT * CC];       // as __half (LN2 out)
__device__ float g_hbuf[(size_t)MTOT * HID];    // as __half (gelu out)
__device__ float g_aphi[NHEAD * NWTOK * NWTOK];
__device__ __half g_wh[3145728];                // fp16 weights: qkv|proj|fc1|fc2

#define WH_QKV  0
#define WH_PROJ 786432
#define WH_FC1  1048576
#define WH_FC2  2097152

__device__ __forceinline__ size_t win_to_nat(int m) {
    int w = m >> 6, n = m & 63;
    int b = w >> 6, wy = (w >> 3) & 7, wx = w & 7;
    int ny = n >> 3, nx = n & 7;
    return (size_t)b * 4096 + (size_t)(wy * 8 + ny) * 64 + (wx * 8 + nx);
}

// ---------------- PTX helpers ----------------
__device__ __forceinline__ uint32_t smem_u32(const void* p) {
    uint32_t a;
    asm("{ .reg .u64 tmp; cvta.to.shared.u64 tmp, %1; cvt.u32.u64 %0, tmp; }"
        : "=r"(a) : "l"(p));
    return a;
}
__device__ __forceinline__ void cp16(uint32_t smem, const void* g) {
    asm volatile("cp.async.cg.shared.global [%0], [%1], 16;\n" :: "r"(smem), "l"(g));
}
__device__ __forceinline__ void cp_commit() {
    asm volatile("cp.async.commit_group;\n" ::: "memory");
}
template <int N>
__device__ __forceinline__ void cp_wait() {
    asm volatile("cp.async.wait_group %0;\n" :: "n"(N) : "memory");
}
__device__ __forceinline__ void ldsm_x4(uint32_t* r, uint32_t addr) {
    asm volatile("ldmatrix.sync.aligned.m8n8.x4.shared.b16 {%0,%1,%2,%3}, [%4];"
                 : "=r"(r[0]), "=r"(r[1]), "=r"(r[2]), "=r"(r[3]) : "r"(addr));
}
__device__ __forceinline__ void ldsm_x2(uint32_t* r, uint32_t addr) {
    asm volatile("ldmatrix.sync.aligned.m8n8.x2.shared.b16 {%0,%1}, [%2];"
                 : "=r"(r[0]), "=r"(r[1]) : "r"(addr));
}
__device__ __forceinline__ void ldsm_x2_trans(uint32_t* r, uint32_t addr) {
    asm volatile("ldmatrix.sync.aligned.m8n8.x2.trans.shared.b16 {%0,%1}, [%2];"
                 : "=r"(r[0]), "=r"(r[1]) : "r"(addr));
}
__device__ __forceinline__ void mma_f16(float* c, const uint32_t* a, const uint32_t* b) {
    asm volatile(
        "mma.sync.aligned.m16n8k16.row.col.f32.f16.f16.f32 "
        "{%0,%1,%2,%3}, {%4,%5,%6,%7}, {%8,%9}, {%0,%1,%2,%3};\n"
        : "+f"(c[0]), "+f"(c[1]), "+f"(c[2]), "+f"(c[3])
        : "r"(a[0]), "r"(a[1]), "r"(a[2]), "r"(a[3]), "r"(b[0]), "r"(b[1]));
}
__device__ __forceinline__ uint32_t pack2(float a, float b) {
    __half2 h = __floats2half2_rn(a, b);
    return *reinterpret_cast<uint32_t*>(&h);
}

// ---------------- weight fp32 -> fp16 ----------------
__global__ void w2h_kernel(const float* __restrict__ w, __half* __restrict__ o, int n) {
    for (int i = blockIdx.x * blockDim.x + threadIdx.x; i < n; i += gridDim.x * blockDim.x)
        o[i] = __float2half_rn(w[i]);
}

// ---------------- A_phi precompute ----------------
__global__ void aphi_kernel(const float* __restrict__ a_p,
                            const float* __restrict__ b_p,
                            float* __restrict__ aphi) {
    int i = blockIdx.x, j = threadIdx.x;
    int az = (i & 7) - (j & 7);
    int ip = (az + 15) % 15;
    float azf = (float)az * (2.0f * PI_F / (float)W_RES);
    float c = cosf(azf), s = sinf(azf);
#pragma unroll
    for (int h = 0; h < NHEAD; h++)
        aphi[((h * 64 + i) << 6) + j] = a_p[ip * NHEAD + h] * c + b_p[ip * NHEAD + h] * s;
}

// ---------------- LayerNorm (fp32 in, fp16 out) ----------------
template <int WINDOWED>
__global__ __launch_bounds__(128) void ln_kernel(const float* __restrict__ x,
                                                 const float* __restrict__ gamma,
                                                 const float* __restrict__ beta,
                                                 __half* __restrict__ out) {
    int m = blockIdx.x;
    size_t src = WINDOWED ? win_to_nat(m) : (size_t)m;
    int t = threadIdx.x;

    const float4 v = *(const float4*)(x + src * CC + t * 4);
    float s  = v.x + v.y + v.z + v.w;
    float s2 = v.x * v.x + v.y * v.y + v.z * v.z + v.w * v.w;
#pragma unroll
    for (int o = 16; o > 0; o >>= 1) {
        s  += __shfl_down_sync(0xffffffffu, s,  o);
        s2 += __shfl_down_sync(0xffffffffu, s2, o);
    }
    __shared__ float sh[8];
    int wr = t >> 5, ln = t & 31;
    if (ln == 0) { sh[wr] = s; sh[wr + 4] = s2; }
    __syncthreads();
    float ts  = sh[0] + sh[1] + sh[2] + sh[3];
    float ts2 = sh[4] + sh[5] + sh[6] + sh[7];
    float mean = ts * (1.0f / CC);
    float var  = ts2 * (1.0f / CC) - mean * mean;
    float rstd = rsqrtf(var + 1e-5f);

    const float4 g4 = *(const float4*)(gamma + t * 4);
    const float4 b4 = *(const float4*)(beta  + t * 4);
    __half2 p0 = __floats2half2_rn((v.x - mean) * rstd * g4.x + b4.x,
                                   (v.y - mean) * rstd * g4.y + b4.y);
    __half2 p1 = __floats2half2_rn((v.z - mean) * rstd * g4.z + b4.z,
                                   (v.w - mean) * rstd * g4.w + b4.w);
    *(__half2*)(out + (size_t)m * CC + t * 4)     = p0;
    *(__half2*)(out + (size_t)m * CC + t * 4 + 2) = p1;
}

// ---------------- fp16 tensor-core GEMM ----------------
#define STRH      72
#define ROWB      144
#define A_ST_B    (128 * ROWB)
#define STAGE_B   (2 * A_ST_B)
#define HGEMM_SMEM (2 * STAGE_B)

template <int EPI>
__global__ __launch_bounds__(256, 2)
void hgemm(const __half* __restrict__ A, const __half* __restrict__ B, int K,
           const float* __restrict__ bias, const float* __restrict__ add,
           float* __restrict__ out) {
    extern __shared__ __half sh[];
    const uint32_t sbase = smem_u32(sh);

    const int bn = blockIdx.x, bm = blockIdx.y;
    const int t = threadIdx.x;
    const int lane = t & 31, wid = t >> 5;
    const int wm = wid >> 2, wn = wid & 3;
    const int g = lane >> 2, tg = lane & 3;

    const __half* Ag = A + (size_t)(bm * 128) * K;
    const __half* Bg = B + (size_t)(bn * 128) * K;

    float c[4][4][4];
#pragma unroll
    for (int a = 0; a < 4; a++)
#pragma unroll
        for (int b = 0; b < 4; b++)
#pragma unroll
            for (int d = 0; d < 4; d++) c[a][b][d] = 0.0f;

    const int nk = K >> 6;

    auto load_stage = [&](int cidx) {
        const uint32_t sb = sbase + (uint32_t)(cidx & 1) * STAGE_B;
        const __half* Ac = Ag + cidx * 64;
        const __half* Bc = Bg + cidx * 64;
#pragma unroll
        for (int i = 0; i < 4; i++) {
            int gr = i * 256 + t;
            int row = gr >> 3, q = gr & 7;
            cp16(sb + row * ROWB + q * 16, Ac + (size_t)row * K + q * 8);
        }
#pragma unroll
        for (int i = 0; i < 4; i++) {
            int gr = i * 256 + t;
            int row = gr >> 3, q = gr & 7;
            cp16(sb + A_ST_B + row * ROWB + q * 16, Bc + (size_t)row * K + q * 8);
        }
        cp_commit();
    };

    load_stage(0);

    for (int cc = 0; cc < nk; cc++) {
        if (cc + 1 < nk) { load_stage(cc + 1); cp_wait<1>(); }
        else             { cp_wait<0>(); }
        __syncthreads();

        const uint32_t sb = sbase + (uint32_t)(cc & 1) * STAGE_B;
        const uint32_t aoff = sb + (wm * 64 + (lane & 15)) * ROWB + (lane >> 4) * 16;
        const uint32_t boff = sb + A_ST_B + (wn * 32 + (lane & 7)) * ROWB + ((lane >> 3) & 1) * 16;

#pragma unroll
        for (int ks = 0; ks < 4; ks++) {
            const uint32_t kb = ks * 32;
            uint32_t af[4][4], bf[4][2];
#pragma unroll
            for (int mi = 0; mi < 4; mi++) ldsm_x4(af[mi], aoff + mi * (16 * ROWB) + kb);
#pragma unroll
            for (int ni = 0; ni < 4; ni++) ldsm_x2(bf[ni], boff + ni * (8 * ROWB) + kb);
#pragma unroll
            for (int mi = 0; mi < 4; mi++)
#pragma unroll
                for (int ni = 0; ni < 4; ni++)
                    mma_f16(c[mi][ni], af[mi], bf[ni]);
        }
        __syncthreads();
    }

#pragma unroll
    for (int mi = 0; mi < 4; mi++) {
#pragma unroll
        for (int half = 0; half < 2; half++) {
            const int m = bm * 128 + wm * 64 + mi * 16 + g + half * 8;
#pragma unroll
            for (int ni = 0; ni < 4; ni++) {
                const int n = bn * 128 + wn * 32 + ni * 8 + 2 * tg;
                float v0 = c[mi][ni][half * 2 + 0];
                float v1 = c[mi][ni][half * 2 + 1];
                if (EPI == 0) {            // QKV: bias + scatter to fp16 planes
                    __half* oh = (__half*)out;
                    int w = m >> 6, nn = m & 63;
                    int which = n >> 9, r = n & 511;
                    int h = r >> 5, d = r & 31;
                    size_t idx = (size_t)which * PLANE +
                                 ((((size_t)w * NHEAD + h) * NWTOK + nn) << 5) + d;
                    *(__half2*)&oh[idx] = __floats2half2_rn(v0 + bias[n], v1 + bias[n + 1]);
                } else if (EPI == 1) {     // proj: window-reverse + residual (fp32)
                    size_t gi = win_to_nat(m);
                    const float2 a2 = *(const float2*)&add[gi * CC + n];
                    float2 o;
                    o.x = v0 + bias[n] + a2.x;
                    o.y = v1 + bias[n + 1] + a2.y;
                    *(float2*)&out[gi * CC + n] = o;
                } else if (EPI == 2) {     // fc1 + exact GELU -> fp16
                    float z0 = v0 + bias[n];
                    float z1 = v1 + bias[n + 1];
                    float g0 = 0.5f * z0 * (1.0f + erff(z0 * 0.70710678118654752440f));
                    float g1 = 0.5f * z1 * (1.0f + erff(z1 * 0.70710678118654752440f));
                    __half* oh = (__half*)out;
                    *(__half2*)&oh[(size_t)m * HID + n] = __floats2half2_rn(g0, g1);
                } else {                   // fc2 + residual (fp32 final)
                    const float2 a2 = *(const float2*)&add[(size_t)m * CC + n];
                    float2 o;
                    o.x = v0 + bias[n] + a2.x;
                    o.y = v1 + bias[n + 1] + a2.y;
                    *(float2*)&out[(size_t)m * CC + n] = o;
                }
            }
        }
    }
}

// ---------------- tensor-core windowed attention ----------------
// Block: one window x 4 heads (grid 1024 x 4), 256 threads, warp = (head, 32 rows).
// smem: Q/K/V tiles fp16 [which][head][64][40] (80B rows: LDSM conflict-free),
//       ct/st sincos tables (15x64 f32), per-head a_r/b_r.

#define ATT_ROWH   40
#define ATT_ROWB   80
#define ATT_TILE_B (64 * ATT_ROWB)          // 5120 per (which, head)
#define ATT_WHICH_B (4 * ATT_TILE_B)        // 20480
#define ATT_CT_OFF  (3 * ATT_WHICH_B)       // 61440
#define ATT_ST_OFF  (ATT_CT_OFF + 3840)     // 65280
#define ATT_AR_OFF  (ATT_ST_OFF + 3840)     // 69120
#define ATT_BR_OFF  (ATT_AR_OFF + 240)      // 69360
#define ATT_SMEM    69632

__global__ __launch_bounds__(256)
void attn_mma_kernel(const float* __restrict__ D,
                     const float* __restrict__ a_r,
                     const float* __restrict__ b_r,
                     const float* __restrict__ aphi,
                     const __half* __restrict__ qkv,
                     __half* __restrict__ outbuf) {
    extern __shared__ __align__(16) char smraw[];
    const uint32_t sbase = smem_u32(smraw);
    float* ctp = (float*)(smraw + ATT_CT_OFF);
    float* stp = (float*)(smraw + ATT_ST_OFF);
    float* arp = (float*)(smraw + ATT_AR_OFF);
    float* brp = (float*)(smraw + ATT_BR_OFF);

    const int w  = blockIdx.x;
    const int h0 = blockIdx.y * 4;
    const int t  = threadIdx.x;
    const int lane = t & 31, wid = t >> 5;
    const int g = lane >> 2, tg = lane & 3;

    // ---- async load Q/K/V tiles for 4 heads (3072 x 16B chunks, 12/thread) ----
#pragma unroll
    for (int i = 0; i < 12; i++) {
        int idx = i * 256 + t;
        int which = idx >> 10;
        int rem = idx & 1023;
        int lh = rem >> 8;
        int row = (rem >> 2) & 63;
        int q = rem & 3;
        const __half* src = qkv + (size_t)which * PLANE +
                            ((((size_t)w * NHEAD + h0 + lh) * NWTOK + row) << 5) + q * 8;
        cp16(sbase + which * ATT_WHICH_B + lh * ATT_TILE_B + row * ATT_ROWB + q * 16, src);
    }
    cp_commit();

    // ---- per-window sincos tables (shared across heads) ----
    {
        const float KR = 2.0f * PI_F / 256.0f;
        int b = w >> 6, wy = (w >> 3) & 7, wx = w & 7;
        for (int idx = t; idx < 960; idx += 256) {
            int r = idx >> 6, j = idx & 63;
            int ny = j >> 3, nx = j & 7;
            float dj = D[(size_t)b * 4096 + (size_t)(wy * 8 + ny) * 64 + (wx * 8 + nx)];
            float ss, cc;
            __sincosf((float)(r - 7) * dj * KR, &ss, &cc);
            ctp[idx] = cc;
            stp[idx] = ss;
        }
    }
    if (t < 60) {
        int lh = t / 15, r = t % 15;
        arp[t] = a_r[r * NHEAD + h0 + lh];
        brp[t] = b_r[r * NHEAD + h0 + lh];
    }
    cp_wait<0>();
    __syncthreads();

    // ---- warp assignment ----
    const int lh = wid >> 1;
    const int h  = h0 + lh;
    const int r0 = (wid & 1) * 32;
    const uint32_t qb = sbase + 0 * ATT_WHICH_B + lh * ATT_TILE_B;
    const uint32_t kb = sbase + 1 * ATT_WHICH_B + lh * ATT_TILE_B;
    const uint32_t vb = sbase + 2 * ATT_WHICH_B + lh * ATT_TILE_B;

    // Q fragments: [mt][kt]
    uint32_t qf[2][2][4];
#pragma unroll
    for (int mt = 0; mt < 2; mt++)
#pragma unroll
        for (int kt = 0; kt < 2; kt++)
            ldsm_x4(qf[mt][kt],
                    qb + (r0 + mt * 16 + (lane & 15)) * ATT_ROWB + (lane >> 4) * 16 + kt * 32);

    // ---- S = Q K^T ----
    float sf[2][8][4];
#pragma unroll
    for (int nt = 0; nt < 8; nt++) {
        uint32_t kf[2][2];
#pragma unroll
        for (int kt = 0; kt < 2; kt++)
            ldsm_x2(kf[kt],
                    kb + (nt * 8 + (lane & 7)) * ATT_ROWB + ((lane >> 3) & 1) * 16 + kt * 32);
#pragma unroll
        for (int mt = 0; mt < 2; mt++) {
            sf[mt][nt][0] = sf[mt][nt][1] = sf[mt][nt][2] = sf[mt][nt][3] = 0.0f;
#pragma unroll
            for (int kt = 0; kt < 2; kt++)
                mma_f16(sf[mt][nt], qf[mt][kt], kf[kt]);
        }
    }

    // ---- bias + scale + row max ----
    const float scale = 0.1767766952966369f;
    float mx[2][2] = {{-1e30f, -1e30f}, {-1e30f, -1e30f}};
#pragma unroll
    for (int mt = 0; mt < 2; mt++) {
        const int i0 = r0 + mt * 16 + g;
        const int i1 = i0 + 8;
        const int yi0 = i0 >> 3, yi1 = i1 >> 3;
        const float* ap0 = aphi + ((h * 64 + i0) << 6);
        const float* ap1 = aphi + ((h * 64 + i1) << 6);
#pragma unroll
        for (int nt = 0; nt < 8; nt++) {
            const int j0 = nt * 8 + 2 * tg;
            // row i0
            {
                int rad = yi0 - nt;
                int rx = rad + 7;
                int ir = rad < 0 ? rad + 15 : rad;
                float ar = arp[lh * 15 + ir], br = brp[lh * 15 + ir];
                float s0 = sf[mt][nt][0] * scale + ap0[j0]     + ar * ctp[rx * 64 + j0]     + br * stp[rx * 64 + j0];
                float s1 = sf[mt][nt][1] * scale + ap0[j0 + 1] + ar * ctp[rx * 64 + j0 + 1] + br * stp[rx * 64 + j0 + 1];
                sf[mt][nt][0] = s0; sf[mt][nt][1] = s1;
                mx[mt][0] = fmaxf(mx[mt][0], fmaxf(s0, s1));
            }
            // row i1
            {
                int rad = yi1 - nt;
                int rx = rad + 7;
                int ir = rad < 0 ? rad + 15 : rad;
                float ar = arp[lh * 15 + ir], br = brp[lh * 15 + ir];
                float s2 = sf[mt][nt][2] * scale + ap1[j0]     + ar * ctp[rx * 64 + j0]     + br * stp[rx * 64 + j0];
                float s3 = sf[mt][nt][3] * scale + ap1[j0 + 1] + ar * ctp[rx * 64 + j0 + 1] + br * stp[rx * 64 + j0 + 1];
                sf[mt][nt][2] = s2; sf[mt][nt][3] = s3;
                mx[mt][1] = fmaxf(mx[mt][1], fmaxf(s2, s3));
            }
        }
    }
    // quad reduction (lanes g*4+tg share a row)
#pragma unroll
    for (int mt = 0; mt < 2; mt++)
#pragma unroll
        for (int hh = 0; hh < 2; hh++) {
            float v = mx[mt][hh];
            v = fmaxf(v, __shfl_xor_sync(0xffffffffu, v, 1));
            v = fmaxf(v, __shfl_xor_sync(0xffffffffu, v, 2));
            mx[mt][hh] = v;
        }

    // ---- exp + row sum; P packed fp16 ----
    uint32_t ph[2][8][2];
    float inv[2][2];
#pragma unroll
    for (int mt = 0; mt < 2; mt++) {
        float sum0 = 0.0f, sum1 = 0.0f;
#pragma unroll
        for (int nt = 0; nt < 8; nt++) {
            float e0 = __expf(sf[mt][nt][0] - mx[mt][0]);
            float e1 = __expf(sf[mt][nt][1] - mx[mt][0]);
            float e2 = __expf(sf[mt][nt][2] - mx[mt][1]);
            float e3 = __expf(sf[mt][nt][3] - mx[mt][1]);
            sum0 += e0 + e1;
            sum1 += e2 + e3;
            ph[mt][nt][0] = pack2(e0, e1);
            ph[mt][nt][1] = pack2(e2, e3);
        }
        sum0 += __shfl_xor_sync(0xffffffffu, sum0, 1);
        sum0 += __shfl_xor_sync(0xffffffffu, sum0, 2);
        sum1 += __shfl_xor_sync(0xffffffffu, sum1, 1);
        sum1 += __shfl_xor_sync(0xffffffffu, sum1, 2);
        inv[mt][0] = 1.0f / sum0;
        inv[mt][1] = 1.0f / sum1;
    }

    // ---- O = P V ----
    float of[2][4][4];
#pragma unroll
    for (int mt = 0; mt < 2; mt++)
#pragma unroll
        for (int vn = 0; vn < 4; vn++)
            of[mt][vn][0] = of[mt][vn][1] = of[mt][vn][2] = of[mt][vn][3] = 0.0f;

#pragma unroll
    for (int kt2 = 0; kt2 < 4; kt2++) {
        uint32_t bv[4][2];
#pragma unroll
        for (int vn = 0; vn < 4; vn++)
            ldsm_x2_trans(bv[vn], vb + (kt2 * 16 + (lane & 15)) * ATT_ROWB + vn * 16);
#pragma unroll
        for (int mt = 0; mt < 2; mt++) {
            uint32_t a[4] = {ph[mt][2 * kt2][0], ph[mt][2 * kt2][1],
                             ph[mt][2 * kt2 + 1][0], ph[mt][2 * kt2 + 1][1]};
#pragma unroll
            for (int vn = 0; vn < 4; vn++)
                mma_f16(of[mt][vn], a, bv[vn]);
        }
    }

    // ---- normalize + write fp16 [token][C] ----
#pragma unroll
    for (int mt = 0; mt < 2; mt++) {
        const int i0 = r0 + mt * 16 + g;
        const int i1 = i0 + 8;
        __half* o0 = outbuf + ((size_t)(w * 64 + i0)) * CC + h * 32 + 2 * tg;
        __half* o1 = outbuf + ((size_t)(w * 64 + i1)) * CC + h * 32 + 2 * tg;
#pragma unroll
        for (int vn = 0; vn < 4; vn++) {
            *(__half2*)(o0 + vn * 8) = __floats2half2_rn(of[mt][vn][0] * inv[mt][0],
                                                         of[mt][vn][1] * inv[mt][0]);
            *(__half2*)(o1 + vn * 8) = __floats2half2_rn(of[mt][vn][2] * inv[mt][1],
                                                         of[mt][vn][3] * inv[mt][1]);
        }
    }
}

// ---------------- launcher ----------------
extern "C" void kernel_launch(void* const* d_in, const int* in_sizes, int n_in,
                              void* d_out, int out_size) {
    const float* x       = (const float*)d_in[0];
    const float* D       = (const float*)d_in[1];
    const float* norm1_g = (const float*)d_in[2];
    const float* norm1_b = (const float*)d_in[3];
    const float* qkv_w   = (const float*)d_in[4];
    const float* qkv_b   = (const float*)d_in[5];
    const float* proj_w  = (const float*)d_in[6];
    const float* proj_b  = (const float*)d_in[7];
    const float* a_p     = (const float*)d_in[8];
    const float* b_p     = (const float*)d_in[9];
    const float* a_r     = (const float*)d_in[10];
    const float* b_r     = (const float*)d_in[11];
    const float* norm2_g = (const float*)d_in[12];
    const float* norm2_b = (const float*)d_in[13];
    const float* fc1_w   = (const float*)d_in[14];
    const float* fc1_b   = (const float*)d_in[15];
    const float* fc2_w   = (const float*)d_in[16];
    const float* fc2_b   = (const float*)d_in[17];
    float* out = (float*)d_out;

    float *xnw, *qkv, *attno, *x2, *xm, *hbuf, *aphi;
    __half* wh;
    cudaGetSymbolAddress((void**)&xnw,   g_xnw);
    cudaGetSymbolAddress((void**)&qkv,   g_qkv);
    cudaGetSymbolAddress((void**)&attno, g_attnout);
    cudaGetSymbolAddress((void**)&x2,    g_x2);
    cudaGetSymbolAddress((void**)&xm,    g_xm);
    cudaGetSymbolAddress((void**)&hbuf,  g_hbuf);
    cudaGetSymbolAddress((void**)&aphi,  g_aphi);
    cudaGetSymbolAddress((void**)&wh,    g_wh);

    __half* xnw_h   = (__half*)xnw;
    __half* qkv_h   = (__half*)qkv;
    __half* attno_h = (__half*)attno;
    __half* xm_h    = (__half*)xm;
    __half* hbuf_h  = (__half*)hbuf;

    static int smem_set = 0;
    if (!smem_set) {
        cudaFuncSetAttribute(hgemm<0>, cudaFuncAttributeMaxDynamicSharedMemorySize, HGEMM_SMEM);
        cudaFuncSetAttribute(hgemm<1>, cudaFuncAttributeMaxDynamicSharedMemorySize, HGEMM_SMEM);
        cudaFuncSetAttribute(hgemm<2>, cudaFuncAttributeMaxDynamicSharedMemorySize, HGEMM_SMEM);
        cudaFuncSetAttribute(hgemm<3>, cudaFuncAttributeMaxDynamicSharedMemorySize, HGEMM_SMEM);
        cudaFuncSetAttribute(attn_mma_kernel, cudaFuncAttributeMaxDynamicSharedMemorySize, ATT_SMEM);
        smem_set = 1;
    }

    // weight conversions
    w2h_kernel<<<384, 256>>>(qkv_w,  wh + WH_QKV,  786432);
    w2h_kernel<<<128, 256>>>(proj_w, wh + WH_PROJ, 262144);
    w2h_kernel<<<512, 256>>>(fc1_w,  wh + WH_FC1,  1048576);
    w2h_kernel<<<512, 256>>>(fc2_w,  wh + WH_FC2,  1048576);

    aphi_kernel<<<64, 64>>>(a_p, b_p, aphi);
    ln_kernel<1><<<MTOT, 128>>>(x, norm1_g, norm1_b, xnw_h);
    hgemm<0><<<dim3(12, 512), 256, HGEMM_SMEM>>>(xnw_h, wh + WH_QKV, 512, qkv_b, nullptr, (float*)qkv_h);
    attn_mma_kernel<<<dim3(NWIN, 4), 256, ATT_SMEM>>>(D, a_r, b_r, aphi, qkv_h, attno_h);
    hgemm<1><<<dim3(4, 512), 256, HGEMM_SMEM>>>(attno_h, wh + WH_PROJ, 512, proj_b, x, x2);
    ln_kernel<0><<<MTOT, 128>>>(x2, norm2_g, norm2_b, xm_h);
    hgemm<2><<<dim3(16, 512), 256, HGEMM_SMEM>>>(xm_h, wh + WH_FC1, 512, fc1_b, nullptr, (float*)hbuf_h);
    hgemm<3><<<dim3(4, 512), 256, HGEMM_SMEM>>>(hbuf_h, wh + WH_FC2, 2048, fc2_b, x2, out);
}